// round 11
// baseline (speedup 1.0000x reference)
#include <cuda_runtime.h>
#include <cuda_bf16.h>

// CapsuleLinear k-means routing (dot sim, no squash) — GB300 sm_103a, round 10.
//
// Reformulation (priors never materialized):
//   logits[n] = (W^T out_n)·x[n],  out ∝ W t,  t = Σ_n e_n x[n]
//   v = M t / sqrt(t^T M t),  M = W^T W  (8x8 per o, in smem)
// Softmax max-free; unnormalized except final iteration (scale invariance).
//
// Round-10: r6 (o-pair FFMA2, fused k-pass — empirical best) + occupancy:
// NREG 7->4, launch_bounds(128,5) => ~100 regs, 5 CTAs/SM, occ ~30%.
// Fused pass means each streamed row costs ONE LDG.128-pair per iteration.

namespace {
constexpr int BATCH   = 64;
constexpr int N_IN    = 1152;
constexpr int LI      = 8;
constexpr int LO      = 16;
constexpr int O_CAPS  = 64;
constexpr int THREADS = 128;
constexpr int NPT     = 9;            // 1152 = 128 * 9
constexpr int NREG    = 4;            // rows kept in registers; 5 streamed via L1
constexpr int NW      = THREADS / 32; // 4 warps
constexpr unsigned FULL = 0xffffffffu;
constexpr float LOG2E = 1.4426950408889634f;
}

// ---- f32x2 packed helpers ----
__device__ __forceinline__ unsigned long long pk2(float lo, float hi) {
    unsigned long long r;
    asm("mov.b64 %0, {%1, %2};" : "=l"(r) : "f"(lo), "f"(hi));
    return r;
}
__device__ __forceinline__ void upk2(float& lo, float& hi, unsigned long long v) {
    asm("mov.b64 {%0, %1}, %2;" : "=f"(lo), "=f"(hi) : "l"(v));
}
__device__ __forceinline__ unsigned long long ffma2(unsigned long long a,
                                                    unsigned long long b,
                                                    unsigned long long c) {
    unsigned long long d;
    asm("fma.rn.f32x2 %0, %1, %2, %3;" : "=l"(d) : "l"(a), "l"(b), "l"(c));
    return d;
}
__device__ __forceinline__ unsigned long long fadd2(unsigned long long a,
                                                    unsigned long long b) {
    unsigned long long d;
    asm("add.rn.f32x2 %0, %1, %2;" : "=l"(d) : "l"(a), "l"(b));
    return d;
}
__device__ __forceinline__ float ex2(float x) {
    float r;
    asm("ex2.approx.f32 %0, %1;" : "=f"(r) : "f"(x));
    return r;
}

__global__ __launch_bounds__(THREADS, 5)
void caps_route_kernel(const float* __restrict__ x,
                       const float* __restrict__ wgt,
                       float* __restrict__ out_c,
                       float* __restrict__ out_p)
{
    const int bo2  = blockIdx.x;          // b*32 + opair (o fastest -> L2/L1 reuse of x[b])
    const int b    = bo2 >> 5;
    const int o0   = (bo2 & 31) << 1;     // this CTA handles o0, o0+1
    const int tid  = threadIdx.x;
    const int lane = tid & 31;
    const int warp = tid >> 5;

    __shared__ float ws[2 * LO * LI];      // weights for o0, o1
    __shared__ float Msh[2 * LI * LI];     // M = W^T W for o0, o1
    __shared__ float tred[2][16][NW];      // t partials, comp-major ([ti][warp] = LDS.128 row)
    __shared__ float sred[NW][2];          // final softmax sums

    const float* wb = wgt + (size_t)o0 * LO * LI;
    ws[tid]       = wb[tid];
    ws[tid + 128] = wb[tid + 128];

    // Row n = tid + k*128 lives at xrow + k*1024 floats. k<NREG cached in regs.
    const float* xrow = x + ((size_t)b * N_IN + tid) * LI;
    float xr[NREG][LI];
    #pragma unroll
    for (int k = 0; k < NREG; k++) {
        const float4* p = reinterpret_cast<const float4*>(xrow + k * THREADS * LI);
        float4 a = p[0], c = p[1];
        xr[k][0] = a.x; xr[k][1] = a.y; xr[k][2] = a.z; xr[k][3] = a.w;
        xr[k][4] = c.x; xr[k][5] = c.y; xr[k][6] = c.z; xr[k][7] = c.w;
    }

    // Packed butterfly: reduce v[16] across warp in 16 shfls; write [comp][warp].
    auto bstore16 = [&](const float v[16], float dst[16][NW]) {
        const bool h16 = (lane & 16);
        float a[8];
        #pragma unroll
        for (int j = 0; j < 8; j++) {
            float send = h16 ? v[j] : v[j + 8];
            float keep = h16 ? v[j + 8] : v[j];
            a[j] = keep + __shfl_xor_sync(FULL, send, 16);
        }
        const bool h8 = (lane & 8);
        float bb[4];
        #pragma unroll
        for (int j = 0; j < 4; j++) {
            float send = h8 ? a[j] : a[j + 4];
            float keep = h8 ? a[j + 4] : a[j];
            bb[j] = keep + __shfl_xor_sync(FULL, send, 8);
        }
        const bool h4 = (lane & 4);
        float cc[2];
        #pragma unroll
        for (int j = 0; j < 2; j++) {
            float send = h4 ? bb[j] : bb[j + 2];
            float keep = h4 ? bb[j + 2] : bb[j];
            cc[j] = keep + __shfl_xor_sync(FULL, send, 4);
        }
        const bool h2 = (lane & 2);
        float send = h2 ? cc[0] : cc[1];
        float keep = h2 ? cc[1] : cc[0];
        float d = keep + __shfl_xor_sync(FULL, send, 2);
        d += __shfl_xor_sync(FULL, d, 1);
        if (!(lane & 1)) dst[(lane >> 1) & 15][warp] = d;
    };

    // ---- init: t = sum over all 9 rows (scale-free), duplicated into both halves ----
    {
        float s[LI];
        #pragma unroll
        for (int i = 0; i < LI; i++) {
            float s01 = xr[0][i] + xr[1][i];
            float s23 = xr[2][i] + xr[3][i];
            s[i] = s01 + s23;
        }
        #pragma unroll
        for (int k = NREG; k < NPT; k++) {
            const float4* p = reinterpret_cast<const float4*>(xrow + k * THREADS * LI);
            float4 a = p[0], c = p[1];
            s[0] += a.x; s[1] += a.y; s[2] += a.z; s[3] += a.w;
            s[4] += c.x; s[5] += c.y; s[6] += c.z; s[7] += c.w;
        }
        float t16[16];
        #pragma unroll
        for (int i = 0; i < LI; i++) { t16[i] = s[i]; t16[i + 8] = s[i]; }
        bstore16(t16, tred[0]);
    }
    __syncthreads();   // ws + tred[0] visible

    // ---- M = W^T W for both o's (one entry per thread) ----
    {
        const int osel = tid >> 6;
        const int idx  = tid & 63;
        const int i = idx >> 3, j = idx & 7;
        const float* wsb = ws + osel * LO * LI;
        float m = 0.0f;
        #pragma unroll
        for (int l = 0; l < LO; l++) m = fmaf(wsb[l * LI + i], wsb[l * LI + j], m);
        Msh[tid] = m;
    }
    __syncthreads();   // Msh visible

    unsigned long long e2[NPT];   // packed (e_o0, e_o1), last iter survives for store

    #pragma unroll
    for (int it = 0; it < 3; it++) {
        const int rb = it & 1;

        // -- per-segment epilogue: lanes {0-7,16-23} -> o0, {8-15,24-31} -> o1 --
        const int i8   = lane & 7;
        const int osel = (lane >> 3) & 1;
        const int ti   = osel * 8 + i8;
        float4 tp = *reinterpret_cast<const float4*>(&tred[rb][ti][0]);
        float tl = (tp.x + tp.y) + (tp.z + tp.w);
        float g = 0.0f;
        const float* Mrow = Msh + osel * 64 + i8 * LI;
        #pragma unroll
        for (int j = 0; j < LI; j++) {
            float tj = __shfl_sync(FULL, tl, j, 8);    // broadcast within 8-lane segment
            g = fmaf(Mrow[j], tj, g);
        }
        float sq = tl * g;
        sq += __shfl_xor_sync(FULL, sq, 4, 8);
        sq += __shfl_xor_sync(FULL, sq, 2, 8);
        sq += __shfl_xor_sync(FULL, sq, 1, 8);
        float vi = g * (rsqrtf(sq) * LOG2E);   // log2e folded -> raw ex2 later

        // -- gather packed v: vp2[j] = (v_o0[j], v_o1[j]) --
        unsigned long long vp2[LI];
        #pragma unroll
        for (int j = 0; j < LI; j++) {
            float v0 = __shfl_sync(FULL, vi, j, 16);
            float v1 = __shfl_sync(FULL, vi, 8 + j, 16);
            vp2[j] = pk2(v0, v1);
        }

        // -- fused k-pass: logits (FFMA2) -> ex2 -> t-update (FFMA2) --
        unsigned long long tp2[LI];
        #pragma unroll
        for (int i = 0; i < LI; i++) tp2[i] = 0ull;

        #pragma unroll
        for (int k = 0; k < NPT; k++) {
            float r[LI];
            if (k < NREG) {
                #pragma unroll
                for (int i = 0; i < LI; i++) r[i] = xr[k][i];
            } else {
                const float4* p = reinterpret_cast<const float4*>(xrow + k * THREADS * LI);
                float4 a = p[0], c = p[1];
                r[0] = a.x; r[1] = a.y; r[2] = a.z; r[3] = a.w;
                r[4] = c.x; r[5] = c.y; r[6] = c.z; r[7] = c.w;
            }
            unsigned long long rr2[LI];
            #pragma unroll
            for (int j = 0; j < LI; j++) rr2[j] = pk2(r[j], r[j]);

            unsigned long long A2 = 0ull;
            #pragma unroll
            for (int j = 0; j < LI; j++) A2 = ffma2(vp2[j], rr2[j], A2);

            float a0, a1; upk2(a0, a1, A2);
            e2[k] = pk2(ex2(a0), ex2(a1));

            #pragma unroll
            for (int i = 0; i < LI; i++) tp2[i] = ffma2(e2[k], rr2[i], tp2[i]);
        }

        // last iteration: reduce both softmax sums (packed adds, 2-value butterfly)
        if (it == 2) {
            unsigned long long s01 = fadd2(e2[0], e2[1]);
            unsigned long long s23 = fadd2(e2[2], e2[3]);
            unsigned long long s45 = fadd2(e2[4], e2[5]);
            unsigned long long s67 = fadd2(e2[6], e2[7]);
            unsigned long long sp  = fadd2(fadd2(fadd2(s01, s23), fadd2(s45, s67)), e2[8]);
            float s0, s1; upk2(s0, s1, sp);
            const bool h16 = (lane & 16);
            float send = h16 ? s0 : s1;
            float keep = h16 ? s1 : s0;
            float s = keep + __shfl_xor_sync(FULL, send, 16);
            s += __shfl_xor_sync(FULL, s, 8);
            s += __shfl_xor_sync(FULL, s, 4);
            s += __shfl_xor_sync(FULL, s, 2);
            s += __shfl_xor_sync(FULL, s, 1);
            if ((lane & 15) == 0) sred[warp][lane >> 4] = s;
        }

        // -- unpack packed t accumulators and reduce --
        float t16[16];
        #pragma unroll
        for (int i = 0; i < LI; i++) upk2(t16[i], t16[i + 8], tp2[i]);
        bstore16(t16, tred[rb ^ 1]);
        __syncthreads();
    }

    // ---- outputs ----
    const float S0 = sred[0][0] + sred[1][0] + sred[2][0] + sred[3][0];
    const float S1 = sred[0][1] + sred[1][1] + sred[2][1] + sred[3][1];
    const float inv0 = __fdividef(1.0f, S0);
    const float inv1 = __fdividef(1.0f, S1);

    float* pp0 = out_p + (size_t)(b * O_CAPS + o0) * N_IN;
    float* pp1 = pp0 + N_IN;
    #pragma unroll
    for (int k = 0; k < NPT; k++) {
        float a0, a1; upk2(a0, a1, e2[k]);
        pp0[tid + k * THREADS] = a0 * inv0;
        pp1[tid + k * THREADS] = a1 * inv1;
    }

    if (tid < 32) {   // final centroids (iter2 wrote tred buf 1)
        const int osel = tid >> 4;
        const int l    = tid & 15;
        const float* wsb = ws + osel * LO * LI + l * LI;
        float a = 0.0f;
        #pragma unroll
        for (int j = 0; j < LI; j++) {
            const int ti = osel * 8 + j;
            float tj = (tred[1][ti][0] + tred[1][ti][1]) + (tred[1][ti][2] + tred[1][ti][3]);
            a = fmaf(wsb[j], tj, a);
        }
        out_c[(size_t)(b * O_CAPS + o0 + osel) * LO + l] = a * (osel ? inv1 : inv0);
    }
}

extern "C" void kernel_launch(void* const* d_in, const int* in_sizes, int n_in,
                              void* d_out, int out_size)
{
    const float* x = (const float*)d_in[0];   // [64,1152,8]
    const float* w = (const float*)d_in[1];   // [64,16,8]
    float* out_c = (float*)d_out;                          // [64,64,16]
    float* out_p = out_c + (size_t)BATCH * O_CAPS * LO;    // [64,64,1152]

    caps_route_kernel<<<BATCH * O_CAPS / 2, THREADS>>>(x, w, out_c, out_p);
}

// round 12
// speedup vs baseline: 1.1892x; 1.1892x over previous
#include <cuda_runtime.h>
#include <cuda_bf16.h>

// CapsuleLinear k-means routing (dot sim, no squash) — GB300 sm_103a, round 12.
//
// Reformulation (priors never materialized):
//   logits[n] = (W^T out_n)·x[n],  out ∝ W t,  t = Σ_n e_n x[n]
//   v = M t / sqrt(t^T M t),  M = W^T W  (8x8 per o, in smem)
// Softmax max-free; unnormalized except final iteration (scale invariance).
//
// Round-12 = r6 (empirical best: o-pair FFMA2, fused k-pass, NREG=7, occ4)
// + (1) streamed-row prefetch hoisted above the epilogue,
// + (2) packed-v broadcast through warp-private smem (replaces 16 shfls),
// + (3) dual-accumulator logit chain (halved dep depth before ex2).

namespace {
constexpr int BATCH   = 64;
constexpr int N_IN    = 1152;
constexpr int LI      = 8;
constexpr int LO      = 16;
constexpr int O_CAPS  = 64;
constexpr int THREADS = 128;
constexpr int NPT     = 9;            // 1152 = 128 * 9
constexpr int NREG    = 7;            // rows kept in registers; 2 streamed via L1
constexpr int NSTR    = NPT - NREG;   // 2 streamed rows
constexpr int NW      = THREADS / 32; // 4 warps
constexpr unsigned FULL = 0xffffffffu;
constexpr float LOG2E = 1.4426950408889634f;
}

// ---- f32x2 packed helpers ----
__device__ __forceinline__ unsigned long long pk2(float lo, float hi) {
    unsigned long long r;
    asm("mov.b64 %0, {%1, %2};" : "=l"(r) : "f"(lo), "f"(hi));
    return r;
}
__device__ __forceinline__ void upk2(float& lo, float& hi, unsigned long long v) {
    asm("mov.b64 {%0, %1}, %2;" : "=f"(lo), "=f"(hi) : "l"(v));
}
__device__ __forceinline__ unsigned long long ffma2(unsigned long long a,
                                                    unsigned long long b,
                                                    unsigned long long c) {
    unsigned long long d;
    asm("fma.rn.f32x2 %0, %1, %2, %3;" : "=l"(d) : "l"(a), "l"(b), "l"(c));
    return d;
}
__device__ __forceinline__ unsigned long long fadd2(unsigned long long a,
                                                    unsigned long long b) {
    unsigned long long d;
    asm("add.rn.f32x2 %0, %1, %2;" : "=l"(d) : "l"(a), "l"(b));
    return d;
}
__device__ __forceinline__ float ex2(float x) {
    float r;
    asm("ex2.approx.f32 %0, %1;" : "=f"(r) : "f"(x));
    return r;
}

__global__ __launch_bounds__(THREADS, 4)
void caps_route_kernel(const float* __restrict__ x,
                       const float* __restrict__ wgt,
                       float* __restrict__ out_c,
                       float* __restrict__ out_p)
{
    const int bo2  = blockIdx.x;          // b*32 + opair (o fastest -> L2/L1 reuse of x[b])
    const int b    = bo2 >> 5;
    const int o0   = (bo2 & 31) << 1;     // this CTA handles o0, o0+1
    const int tid  = threadIdx.x;
    const int lane = tid & 31;
    const int warp = tid >> 5;

    __shared__ float ws[2 * LO * LI];                 // weights for o0, o1
    __shared__ float Msh[2 * LI * LI];                // M = W^T W for o0, o1
    __shared__ float tred[2][16][NW];                 // t partials, comp-major
    __shared__ float sred[NW][2];                     // final softmax sums
    __shared__ unsigned long long vsh[NW][LI];        // packed v per warp (warp-private)

    const float* wb = wgt + (size_t)o0 * LO * LI;
    ws[tid]       = wb[tid];
    ws[tid + 128] = wb[tid + 128];

    // Row n = tid + k*128 lives at xrow + k*1024 floats. k<NREG cached in regs.
    const float* xrow = x + ((size_t)b * N_IN + tid) * LI;
    float xr[NREG][LI];
    #pragma unroll
    for (int k = 0; k < NREG; k++) {
        const float4* p = reinterpret_cast<const float4*>(xrow + k * THREADS * LI);
        float4 a = p[0], c = p[1];
        xr[k][0] = a.x; xr[k][1] = a.y; xr[k][2] = a.z; xr[k][3] = a.w;
        xr[k][4] = c.x; xr[k][5] = c.y; xr[k][6] = c.z; xr[k][7] = c.w;
    }

    // Packed butterfly: reduce v[16] across warp in 16 shfls; write [comp][warp].
    auto bstore16 = [&](const float v[16], float dst[16][NW]) {
        const bool h16 = (lane & 16);
        float a[8];
        #pragma unroll
        for (int j = 0; j < 8; j++) {
            float send = h16 ? v[j] : v[j + 8];
            float keep = h16 ? v[j + 8] : v[j];
            a[j] = keep + __shfl_xor_sync(FULL, send, 16);
        }
        const bool h8 = (lane & 8);
        float bb[4];
        #pragma unroll
        for (int j = 0; j < 4; j++) {
            float send = h8 ? a[j] : a[j + 4];
            float keep = h8 ? a[j + 4] : a[j];
            bb[j] = keep + __shfl_xor_sync(FULL, send, 8);
        }
        const bool h4 = (lane & 4);
        float cc[2];
        #pragma unroll
        for (int j = 0; j < 2; j++) {
            float send = h4 ? bb[j] : bb[j + 2];
            float keep = h4 ? bb[j + 2] : bb[j];
            cc[j] = keep + __shfl_xor_sync(FULL, send, 4);
        }
        const bool h2 = (lane & 2);
        float send = h2 ? cc[0] : cc[1];
        float keep = h2 ? cc[1] : cc[0];
        float d = keep + __shfl_xor_sync(FULL, send, 2);
        d += __shfl_xor_sync(FULL, d, 1);
        if (!(lane & 1)) dst[(lane >> 1) & 15][warp] = d;
    };

    // ---- init: t = sum over all 9 rows (scale-free), duplicated into both halves ----
    {
        float s[LI];
        #pragma unroll
        for (int i = 0; i < LI; i++) {
            float s01 = xr[0][i] + xr[1][i];
            float s23 = xr[2][i] + xr[3][i];
            float s45 = xr[4][i] + xr[5][i];
            s[i] = ((s01 + s23) + s45) + xr[6][i];
        }
        #pragma unroll
        for (int k = NREG; k < NPT; k++) {
            const float4* p = reinterpret_cast<const float4*>(xrow + k * THREADS * LI);
            float4 a = p[0], c = p[1];
            s[0] += a.x; s[1] += a.y; s[2] += a.z; s[3] += a.w;
            s[4] += c.x; s[5] += c.y; s[6] += c.z; s[7] += c.w;
        }
        float t16[16];
        #pragma unroll
        for (int i = 0; i < LI; i++) { t16[i] = s[i]; t16[i + 8] = s[i]; }
        bstore16(t16, tred[0]);
    }
    __syncthreads();   // ws + tred[0] visible

    // ---- M = W^T W for both o's (one entry per thread) ----
    {
        const int osel = tid >> 6;
        const int idx  = tid & 63;
        const int i = idx >> 3, j = idx & 7;
        const float* wsb = ws + osel * LO * LI;
        float m = 0.0f;
        #pragma unroll
        for (int l = 0; l < LO; l++) m = fmaf(wsb[l * LI + i], wsb[l * LI + j], m);
        Msh[tid] = m;
    }
    __syncthreads();   // Msh visible

    unsigned long long e2[NPT];   // packed (e_o0, e_o1), last iter survives for store

    #pragma unroll
    for (int it = 0; it < 3; it++) {
        const int rb = it & 1;

        // -- prefetch streamed rows NOW; L1 latency hides behind the epilogue --
        float4 pf[NSTR][2];
        #pragma unroll
        for (int k = 0; k < NSTR; k++) {
            const float4* p = reinterpret_cast<const float4*>(xrow + (NREG + k) * THREADS * LI);
            pf[k][0] = p[0];
            pf[k][1] = p[1];
        }

        // -- per-segment epilogue: lanes {0-7,16-23} -> o0, {8-15,24-31} -> o1 --
        const int i8   = lane & 7;
        const int osel = (lane >> 3) & 1;
        const int ti   = osel * 8 + i8;
        float4 tp = *reinterpret_cast<const float4*>(&tred[rb][ti][0]);
        float tl = (tp.x + tp.y) + (tp.z + tp.w);
        float g = 0.0f;
        const float* Mrow = Msh + osel * 64 + i8 * LI;
        #pragma unroll
        for (int j = 0; j < LI; j++) {
            float tj = __shfl_sync(FULL, tl, j, 8);    // broadcast within 8-lane segment
            g = fmaf(Mrow[j], tj, g);
        }
        float sq = tl * g;
        sq += __shfl_xor_sync(FULL, sq, 4, 8);
        sq += __shfl_xor_sync(FULL, sq, 2, 8);
        sq += __shfl_xor_sync(FULL, sq, 1, 8);
        float vi = g * (rsqrtf(sq) * LOG2E);   // log2e folded -> raw ex2 later

        // -- packed-v broadcast through warp-private smem (1 shfl + STS.64 + 4 LDS.128) --
        float vopp = __shfl_xor_sync(FULL, vi, 8, 16);   // lane j<8 gets v_o1[j]
        if (lane < 8) vsh[warp][lane] = pk2(vi, vopp);
        __syncwarp();
        unsigned long long vp2[LI];
        {
            const ulonglong2* vv = reinterpret_cast<const ulonglong2*>(&vsh[warp][0]);
            ulonglong2 q0 = vv[0], q1 = vv[1], q2 = vv[2], q3 = vv[3];
            vp2[0] = q0.x; vp2[1] = q0.y; vp2[2] = q1.x; vp2[3] = q1.y;
            vp2[4] = q2.x; vp2[5] = q2.y; vp2[6] = q3.x; vp2[7] = q3.y;
        }

        // -- fused k-pass: logits (FFMA2, dual chains) -> ex2 -> t-update (FFMA2) --
        unsigned long long tp2[LI];
        #pragma unroll
        for (int i = 0; i < LI; i++) tp2[i] = 0ull;

        #pragma unroll
        for (int k = 0; k < NPT; k++) {
            float r[LI];
            if (k < NREG) {
                #pragma unroll
                for (int i = 0; i < LI; i++) r[i] = xr[k][i];
            } else {
                float4 a = pf[k - NREG][0], c = pf[k - NREG][1];
                r[0] = a.x; r[1] = a.y; r[2] = a.z; r[3] = a.w;
                r[4] = c.x; r[5] = c.y; r[6] = c.z; r[7] = c.w;
            }
            unsigned long long rr2[LI];
            #pragma unroll
            for (int j = 0; j < LI; j++) rr2[j] = pk2(r[j], r[j]);

            // dual accumulator chains (depth 4 each) + one packed add
            unsigned long long Aa = 0ull, Ab = 0ull;
            #pragma unroll
            for (int j = 0; j < 4; j++) {
                Aa = ffma2(vp2[j],     rr2[j],     Aa);
                Ab = ffma2(vp2[j + 4], rr2[j + 4], Ab);
            }
            unsigned long long A2 = fadd2(Aa, Ab);

            float a0, a1; upk2(a0, a1, A2);
            e2[k] = pk2(ex2(a0), ex2(a1));

            #pragma unroll
            for (int i = 0; i < LI; i++) tp2[i] = ffma2(e2[k], rr2[i], tp2[i]);
        }

        // last iteration: reduce both softmax sums (packed adds, 2-value butterfly)
        if (it == 2) {
            unsigned long long s01 = fadd2(e2[0], e2[1]);
            unsigned long long s23 = fadd2(e2[2], e2[3]);
            unsigned long long s45 = fadd2(e2[4], e2[5]);
            unsigned long long s67 = fadd2(e2[6], e2[7]);
            unsigned long long sp  = fadd2(fadd2(fadd2(s01, s23), fadd2(s45, s67)), e2[8]);
            float s0, s1; upk2(s0, s1, sp);
            const bool h16 = (lane & 16);
            float send = h16 ? s0 : s1;
            float keep = h16 ? s1 : s0;
            float s = keep + __shfl_xor_sync(FULL, send, 16);
            s += __shfl_xor_sync(FULL, s, 8);
            s += __shfl_xor_sync(FULL, s, 4);
            s += __shfl_xor_sync(FULL, s, 2);
            s += __shfl_xor_sync(FULL, s, 1);
            if ((lane & 15) == 0) sred[warp][lane >> 4] = s;
        }

        // -- unpack packed t accumulators and reduce --
        float t16[16];
        #pragma unroll
        for (int i = 0; i < LI; i++) upk2(t16[i], t16[i + 8], tp2[i]);
        bstore16(t16, tred[rb ^ 1]);
        __syncthreads();
    }

    // ---- outputs ----
    const float S0 = sred[0][0] + sred[1][0] + sred[2][0] + sred[3][0];
    const float S1 = sred[0][1] + sred[1][1] + sred[2][1] + sred[3][1];
    const float inv0 = __fdividef(1.0f, S0);
    const float inv1 = __fdividef(1.0f, S1);

    float* pp0 = out_p + (size_t)(b * O_CAPS + o0) * N_IN;
    float* pp1 = pp0 + N_IN;
    #pragma unroll
    for (int k = 0; k < NPT; k++) {
        float a0, a1; upk2(a0, a1, e2[k]);
        pp0[tid + k * THREADS] = a0 * inv0;
        pp1[tid + k * THREADS] = a1 * inv1;
    }

    if (tid < 32) {   // final centroids (iter2 wrote tred buf 1)
        const int osel = tid >> 4;
        const int l    = tid & 15;
        const float* wsb = ws + osel * LO * LI + l * LI;
        float a = 0.0f;
        #pragma unroll
        for (int j = 0; j < LI; j++) {
            const int ti = osel * 8 + j;
            float tj = (tred[1][ti][0] + tred[1][ti][1]) + (tred[1][ti][2] + tred[1][ti][3]);
            a = fmaf(wsb[j], tj, a);
        }
        out_c[(size_t)(b * O_CAPS + o0 + osel) * LO + l] = a * (osel ? inv1 : inv0);
    }
}

extern "C" void kernel_launch(void* const* d_in, const int* in_sizes, int n_in,
                              void* d_out, int out_size)
{
    const float* x = (const float*)d_in[0];   // [64,1152,8]
    const float* w = (const float*)d_in[1];   // [64,16,8]
    float* out_c = (float*)d_out;                          // [64,64,16]
    float* out_p = out_c + (size_t)BATCH * O_CAPS * LO;    // [64,64,1152]

    caps_route_kernel<<<BATCH * O_CAPS / 2, THREADS>>>(x, w, out_c, out_p);
}